// round 10
// baseline (speedup 1.0000x reference)
#include <cuda_runtime.h>

// MultiDense: out[i,j,l] = sum_k x[i,j,k] * params[inds[i], l, k] + params[inds[i], l, 128]
// I=8192, J=32, IN_F=128, OUT_F=128.
//
// One CTA (256 threads) per i. Per-thread tile: 2 j-pairs x 4 columns.
// x staged as j-paired float2 (broadcast LDS.128), W staged padded to 132
// floats/row (aligned, conflict-free float4 loads). Packed f32x2 FMAs
// (bit-exact fp32). 2 CTAs/SM -> 16 warps/SM for latency hiding.

#define I_DIM 8192
#define J_DIM 32
#define IN_F  128
#define OUT_F 128
#define NODE_MASK 4095
#define PROW_SRC 129                      // 128 weights + bias
#define PROW_PAD 132                      // float4-aligned, conflict-free
#define X_FLOATS (J_DIM * IN_F)           // 4096
#define W_SRC_FLOATS (OUT_F * PROW_SRC)   // 16512
#define W_PAD_FLOATS (OUT_F * PROW_PAD)   // 16896
#define XP_PAIRS (X_FLOATS / 2)           // 2048 float2
#define SMEM_BYTES (W_PAD_FLOATS * 4 + XP_PAIRS * 8)   // 67584 + 16384 = 83968

typedef unsigned long long ull;

__device__ __forceinline__ ull ffma2(ull a, ull b, ull c)
{
    ull d;
    asm("fma.rn.f32x2 %0, %1, %2, %3;" : "=l"(d) : "l"(a), "l"(b), "l"(c));
    return d;
}

__device__ __forceinline__ ull pack2(float lo, float hi)
{
    ull d;
    asm("mov.b64 %0, {%1, %2};" : "=l"(d) : "f"(lo), "f"(hi));
    return d;
}

__global__ __launch_bounds__(256, 2)
void multidense_kernel(const float* __restrict__ x_in,
                       const int* __restrict__ inds,
                       const float* __restrict__ params,
                       float* __restrict__ out)
{
    extern __shared__ float smem[];
    float*  Ws = smem;                                            // [128][132]
    float2* Xp = reinterpret_cast<float2*>(smem + W_PAD_FLOATS);  // [16 jpairs][128]

    const int i = blockIdx.x;
    const int t = threadIdx.x;            // 0..255
    const int node = inds[i] & NODE_MASK; // int32 index, masked (can't IMA)

    // ---- stage params row, re-strided 129 -> 132 ----
    // LDG coalesced over idx; STS near-consecutive -> conflict-free.
    {
        const float* pg = params + (size_t)node * W_SRC_FLOATS;
        #pragma unroll 4
        for (int r = 0; r < 65; r++) {
            int idx = t + 256 * r;                 // 0..16511 (+ guard)
            if (idx < W_SRC_FLOATS) {
                int l = idx / PROW_SRC;            // reciprocal-mul by compiler
                int k = idx - l * PROW_SRC;        // 0..128 (128 = bias)
                Ws[l * PROW_PAD + k] = pg[idx];
            }
        }
    }

    // ---- stage x as j-paired float2: Xp[p*128 + k] = (x[2p][k], x[2p+1][k]) ----
    {
        const float* xg = x_in + (size_t)i * X_FLOATS;
        #pragma unroll
        for (int r = 0; r < XP_PAIRS / 256; r++) { // 8 iters
            int idx = t + r * 256;
            int p = idx >> 7;
            int k = idx & 127;
            float a = xg[(2 * p) * IN_F + k];
            float b = xg[(2 * p + 1) * IN_F + k];
            Xp[idx] = make_float2(a, b);
        }
    }

    __syncthreads();

    // ---- compute: cg = column group (4 cols cg+32c), jb = j-block (jpairs 2jb,2jb+1) ----
    const int cg = t & 31;
    const int jb = t >> 5;                 // 0..7

    ull acc[2][4];
    #pragma unroll
    for (int jp = 0; jp < 2; jp++)
        #pragma unroll
        for (int c = 0; c < 4; c++) acc[jp][c] = 0ull;

    // W as float4: column cg base = cg*33 float4s; col stride (32 cols) = 1056.
    const float4* wv = reinterpret_cast<const float4*>(Ws) + cg * (PROW_PAD / 4);
    // x chunks (16B = 2 k-pairs): j-pair p starts at chunk p*64; jb covers p=2jb.
    const ulonglong2* xv = reinterpret_cast<const ulonglong2*>(Xp) + jb * 128;

    #pragma unroll 4
    for (int kk = 0; kk < IN_F / 4; kk++) {
        // W: 4 columns x 4 k via one aligned, conflict-free LDS.128 each.
        ull wq[4][4];
        #pragma unroll
        for (int c = 0; c < 4; c++) {
            const float4 w = wv[c * 1056 + kk];
            wq[c][0] = pack2(w.x, w.x);
            wq[c][1] = pack2(w.y, w.y);
            wq[c][2] = pack2(w.z, w.z);
            wq[c][3] = pack2(w.w, w.w);
        }
        // x: 2 j-pairs x 4 k via two broadcast LDS.128 each.
        #pragma unroll
        for (int jp = 0; jp < 2; jp++) {
            const ulonglong2 v01 = xv[jp * 64 + 2 * kk];      // k-pairs (4kk,4kk+1)
            const ulonglong2 v23 = xv[jp * 64 + 2 * kk + 1];  // k-pairs (4kk+2,4kk+3)
            #pragma unroll
            for (int c = 0; c < 4; c++) {
                ull a = acc[jp][c];
                a = ffma2(v01.x, wq[c][0], a);
                a = ffma2(v01.y, wq[c][1], a);
                a = ffma2(v23.x, wq[c][2], a);
                a = ffma2(v23.y, wq[c][3], a);
                acc[jp][c] = a;
            }
        }
    }

    // ---- epilogue: bias + coalesced stores (warp lanes = consecutive l) ----
    float* og = out + (size_t)i * (J_DIM * OUT_F);
    #pragma unroll
    for (int c = 0; c < 4; c++) {
        const int l = cg + 32 * c;
        const float bias = Ws[l * PROW_PAD + 128];
        #pragma unroll
        for (int jp = 0; jp < 2; jp++) {
            float r0, r1;
            asm("mov.b64 {%0, %1}, %2;" : "=f"(r0), "=f"(r1) : "l"(acc[jp][c]));
            const int j0 = 4 * jb + 2 * jp;
            og[j0       * OUT_F + l] = r0 + bias;
            og[(j0 + 1) * OUT_F + l] = r1 + bias;
        }
    }
}

extern "C" void kernel_launch(void* const* d_in, const int* in_sizes, int n_in,
                              void* d_out, int out_size)
{
    const float* x_in   = (const float*)d_in[0];
    const int*   inds   = (const int*)d_in[1];
    const float* params = (const float*)d_in[2];
    float*       out    = (float*)d_out;

    static bool attr_set = false;
    if (!attr_set) {
        cudaFuncSetAttribute(multidense_kernel,
                             cudaFuncAttributeMaxDynamicSharedMemorySize, SMEM_BYTES);
        attr_set = true;
    }

    multidense_kernel<<<I_DIM, 256, SMEM_BYTES>>>(x_in, inds, params, out);
}

// round 12
// speedup vs baseline: 1.6364x; 1.6364x over previous
#include <cuda_runtime.h>
#include <cuda_bf16.h>
#include <cstdint>

// MultiDense via mma.sync (sm_100 baseline ISA): per i,
// D[j=32, l=128] = x[32,128] @ W[128,128]^T + bias, fp32 via split-bf16
// 3-pass (AhBh + AhBl + AlBh), fp32 accumulators. One CTA (128 thr) per i.

#define I_DIM 8192
#define J_DIM 32
#define IN_F  128
#define OUT_F 128
#define NODE_MASK 4095
#define PROW_SRC 129
#define W_SRC_FLOATS (OUT_F * PROW_SRC)     // 16512

#define RSTRIDE 136                          // bf16 row stride (272B = 17*16B: ldmatrix conflict-free)
// SMEM byte offsets (all 16B-aligned)
#define OFF_WHI 0                            // 128 x 136 bf16 = 34816
#define OFF_WLO 34816
#define OFF_XHI 69632                        // 32 x 136 bf16 = 8704
#define OFF_XLO 78336
#define OFF_BIAS 87040                       // 128 f32
#define SMEM_BYTES 87552

__device__ __forceinline__ uint32_t smem_u32(const void* p) {
    uint32_t a;
    asm("{ .reg .u64 t; cvta.to.shared.u64 t, %1; cvt.u32.u64 %0, t; }" : "=r"(a) : "l"(p));
    return a;
}

__device__ __forceinline__ void ldmx4(uint32_t* r, uint32_t addr) {
    asm volatile("ldmatrix.sync.aligned.m8n8.x4.shared.b16 {%0,%1,%2,%3}, [%4];"
                 : "=r"(r[0]), "=r"(r[1]), "=r"(r[2]), "=r"(r[3]) : "r"(addr));
}

__device__ __forceinline__ void mma_bf16(float* c, const uint32_t* a, uint32_t b0, uint32_t b1) {
    asm volatile(
        "mma.sync.aligned.m16n8k16.row.col.f32.bf16.bf16.f32 "
        "{%0,%1,%2,%3}, {%4,%5,%6,%7}, {%8,%9}, {%0,%1,%2,%3};"
        : "+f"(c[0]), "+f"(c[1]), "+f"(c[2]), "+f"(c[3])
        : "r"(a[0]), "r"(a[1]), "r"(a[2]), "r"(a[3]), "r"(b0), "r"(b1));
}

__global__ __launch_bounds__(128, 2)
void multidense_kernel(const float* __restrict__ x_in,
                       const int* __restrict__ inds,
                       const float* __restrict__ params,
                       float* __restrict__ out)
{
    extern __shared__ char smem[];
    const uint32_t sb = smem_u32(smem);
    float* bias_s = reinterpret_cast<float*>(smem + OFF_BIAS);

    const int i = blockIdx.x;
    const int t = threadIdx.x;            // 0..127
    const int node = inds[i] & NODE_MASK;

    // ---- stage + split x: [32][128] -> Xhi/Xlo bf16 [32][136] ----
    {
        const float* xg = x_in + (size_t)i * (J_DIM * IN_F);
        #pragma unroll
        for (int r = 0; r < 16; r++) {
            int pidx = t + 128 * r;          // k-pair index, 0..2047
            int j = pidx >> 6;
            int k = (pidx & 63) * 2;
            float2 v = *reinterpret_cast<const float2*>(xg + j * IN_F + k);
            __nv_bfloat16 h0 = __float2bfloat16(v.x), h1 = __float2bfloat16(v.y);
            __nv_bfloat162 hp; hp.x = h0; hp.y = h1;
            __nv_bfloat162 lp;
            lp.x = __float2bfloat16(v.x - __bfloat162float(h0));
            lp.y = __float2bfloat16(v.y - __bfloat162float(h1));
            uint32_t o = (uint32_t)(j * RSTRIDE + k) * 2;
            *reinterpret_cast<__nv_bfloat162*>(smem + OFF_XHI + o) = hp;
            *reinterpret_cast<__nv_bfloat162*>(smem + OFF_XLO + o) = lp;
        }
    }

    // ---- stage + split W: [128][129] -> Whi/Wlo bf16 [128][136] + bias ----
    {
        const float* pg = params + (size_t)node * W_SRC_FLOATS;
        #pragma unroll 4
        for (int r = 0; r < 64; r++) {
            int pidx = t + 128 * r;          // 0..8191
            int l = pidx >> 6;
            int k = (pidx & 63) * 2;
            const float* src = pg + l * PROW_SRC + k;   // scalar loads (129-stride: float2 unaligned)
            float v0 = src[0], v1 = src[1];
            __nv_bfloat16 h0 = __float2bfloat16(v0), h1 = __float2bfloat16(v1);
            __nv_bfloat162 hp; hp.x = h0; hp.y = h1;
            __nv_bfloat162 lp;
            lp.x = __float2bfloat16(v0 - __bfloat162float(h0));
            lp.y = __float2bfloat16(v1 - __bfloat162float(h1));
            uint32_t o = (uint32_t)(l * RSTRIDE + k) * 2;
            *reinterpret_cast<__nv_bfloat162*>(smem + OFF_WHI + o) = hp;
            *reinterpret_cast<__nv_bfloat162*>(smem + OFF_WLO + o) = lp;
        }
        bias_s[t] = pg[t * PROW_SRC + IN_F];
    }

    __syncthreads();

    // ---- compute: warp w -> j-rows [j0, j0+16) x l-cols [l0, l0+64) ----
    const int wid = t >> 5, lane = t & 31;
    const int j0 = (wid >> 1) * 16;
    const int l0 = (wid & 1) * 64;

    float c[8][4];                          // 8 n-tiles (8 cols each) x 4 accum
    #pragma unroll
    for (int nt = 0; nt < 8; nt++)
        #pragma unroll
        for (int q = 0; q < 4; q++) c[nt][q] = 0.0f;

    // ldmatrix lane->row maps
    const int arow  = j0 + (lane & 7) + ((lane >> 3) & 1) * 8;  // A tiles: (r0-7,k0)(r8-15,k0)(r0-7,k8)(r8-15,k8)
    const int akoff = (lane >> 4) * 8;
    const int brow  = l0 + (lane & 7) + (lane >> 4) * 8;        // B tiles: (n0-7,k0)(n0-7,k8)(n8-15,k0)(n8-15,k8)
    const int bkoff = ((lane >> 3) & 1) * 8;

    uint32_t a_hi = sb + OFF_XHI + (uint32_t)(arow * RSTRIDE + akoff) * 2;
    uint32_t a_lo = sb + OFF_XLO + (uint32_t)(arow * RSTRIDE + akoff) * 2;
    uint32_t b_hi = sb + OFF_WHI + (uint32_t)(brow * RSTRIDE + bkoff) * 2;
    uint32_t b_lo = sb + OFF_WLO + (uint32_t)(brow * RSTRIDE + bkoff) * 2;
    const uint32_t PSTEP = 16 * RSTRIDE * 2;       // 16 n-rows per pair block

    #pragma unroll
    for (int ks = 0; ks < 8; ks++) {
        const uint32_t ko = (uint32_t)ks * 32;     // 16 bf16 = 32B per k-step
        uint32_t ah[4], al[4];
        ldmx4(ah, a_hi + ko);
        ldmx4(al, a_lo + ko);

        uint32_t bh[4][4], bl[4][4];
        #pragma unroll
        for (int p = 0; p < 4; p++) {
            ldmx4(bh[p], b_hi + p * PSTEP + ko);
            ldmx4(bl[p], b_lo + p * PSTEP + ko);
        }

        #pragma unroll
        for (int nt = 0; nt < 8; nt++) {
            const int p = nt >> 1;
            const int q = (nt & 1) * 2;            // regs {q, q+1} = this n-tile's b0,b1
            mma_bf16(c[nt], ah, bh[p][q], bh[p][q + 1]);   // hi*hi
            mma_bf16(c[nt], ah, bl[p][q], bl[p][q + 1]);   // hi*lo
            mma_bf16(c[nt], al, bh[p][q], bh[p][q + 1]);   // lo*hi
        }
    }

    // ---- epilogue: c0,c1 = row j0+g cols l+0,1 ; c2,c3 = row j0+g+8 ----
    const int g = lane >> 2, tg = lane & 3;
    float* og = out + (size_t)i * (J_DIM * OUT_F);
    #pragma unroll
    for (int nt = 0; nt < 8; nt++) {
        const int l = l0 + nt * 8 + 2 * tg;        // even -> 8B aligned
        const float2 b2 = *reinterpret_cast<const float2*>(bias_s + l);
        float2 r0; r0.x = c[nt][0] + b2.x; r0.y = c[nt][1] + b2.y;
        float2 r1; r1.x = c[nt][2] + b2.x; r1.y = c[nt][3] + b2.y;
        *reinterpret_cast<float2*>(og + (j0 + g)     * OUT_F + l) = r0;
        *reinterpret_cast<float2*>(og + (j0 + g + 8) * OUT_F + l) = r1;
    }
}

extern "C" void kernel_launch(void* const* d_in, const int* in_sizes, int n_in,
                              void* d_out, int out_size)
{
    const float* x_in   = (const float*)d_in[0];
    const int*   inds   = (const int*)d_in[1];
    const float* params = (const float*)d_in[2];
    float*       out    = (float*)d_out;

    static bool attr_set = false;
    if (!attr_set) {
        cudaFuncSetAttribute(multidense_kernel,
                             cudaFuncAttributeMaxDynamicSharedMemorySize, SMEM_BYTES);
        attr_set = true;
    }

    multidense_kernel<<<I_DIM, 128, SMEM_BYTES>>>(x_in, inds, params, out);
}

// round 13
// speedup vs baseline: 2.9897x; 1.8270x over previous
#include <cuda_runtime.h>
#include <cuda_bf16.h>
#include <cstdint>

// MultiDense via mma.sync: per i, D[j=32, l=128] = x @ W^T + bias, split-bf16
// 3-pass (AhBh + AhBl + AlBh), fp32 accum. One CTA (128 thr) per i.
// R13: x kept in registers (no smem), W staging batched for MLP, 3 CTAs/SM.

#define I_DIM 8192
#define J_DIM 32
#define IN_F  128
#define OUT_F 128
#define NODE_MASK 4095
#define PROW_SRC 129
#define W_SRC_FLOATS (OUT_F * PROW_SRC)     // 16512

#define RSTRIDE 136                          // bf16 row stride (272B): ldmatrix conflict-free
#define OFF_WHI 0                            // 128 x 136 bf16 = 34816
#define OFF_WLO 34816
#define OFF_BIAS 69632                       // 128 f32
#define SMEM_BYTES 70144                     // 3 CTAs/SM

__device__ __forceinline__ uint32_t smem_u32(const void* p) {
    uint32_t a;
    asm("{ .reg .u64 t; cvta.to.shared.u64 t, %1; cvt.u32.u64 %0, t; }" : "=r"(a) : "l"(p));
    return a;
}

__device__ __forceinline__ void ldmx4(uint32_t* r, uint32_t addr) {
    asm volatile("ldmatrix.sync.aligned.m8n8.x4.shared.b16 {%0,%1,%2,%3}, [%4];"
                 : "=r"(r[0]), "=r"(r[1]), "=r"(r[2]), "=r"(r[3]) : "r"(addr));
}

__device__ __forceinline__ void mma_bf16(float* c, uint32_t a0, uint32_t a1, uint32_t a2,
                                         uint32_t a3, uint32_t b0, uint32_t b1) {
    asm volatile(
        "mma.sync.aligned.m16n8k16.row.col.f32.bf16.bf16.f32 "
        "{%0,%1,%2,%3}, {%4,%5,%6,%7}, {%8,%9}, {%0,%1,%2,%3};"
        : "+f"(c[0]), "+f"(c[1]), "+f"(c[2]), "+f"(c[3])
        : "r"(a0), "r"(a1), "r"(a2), "r"(a3), "r"(b0), "r"(b1));
}

__device__ __forceinline__ uint32_t cvt_hi(float2 v) {
    __nv_bfloat162 h;
    h.x = __float2bfloat16(v.x);
    h.y = __float2bfloat16(v.y);
    return *reinterpret_cast<uint32_t*>(&h);
}
__device__ __forceinline__ uint32_t cvt_lo(float2 v, uint32_t hi) {
    __nv_bfloat162 h = *reinterpret_cast<__nv_bfloat162*>(&hi);
    __nv_bfloat162 l;
    l.x = __float2bfloat16(v.x - __bfloat162float(h.x));
    l.y = __float2bfloat16(v.y - __bfloat162float(h.y));
    return *reinterpret_cast<uint32_t*>(&l);
}

__global__ __launch_bounds__(128, 3)
void multidense_kernel(const float* __restrict__ x_in,
                       const int* __restrict__ inds,
                       const float* __restrict__ params,
                       float* __restrict__ out)
{
    extern __shared__ char smem[];
    const uint32_t sb = smem_u32(smem);
    float* bias_s = reinterpret_cast<float*>(smem + OFF_BIAS);

    const int i = blockIdx.x;
    const int t = threadIdx.x;            // 0..127
    const int node = inds[i] & NODE_MASK;

    // ---- stage + split W: [128][129] fp32 -> Whi/Wlo bf16 [128][136], batched MLP ----
    {
        const float* pg = params + (size_t)node * W_SRC_FLOATS;
        #pragma unroll
        for (int rb = 0; rb < 8; rb++) {
            float v0[8], v1[8];
            int lv[8], kv[8];
            #pragma unroll
            for (int m = 0; m < 8; m++) {
                int pidx = t + 128 * (rb * 8 + m);       // 0..8191
                lv[m] = pidx >> 6;
                kv[m] = (pidx & 63) * 2;
                const float* s = pg + lv[m] * PROW_SRC + kv[m];
                v0[m] = s[0];                            // 16 LDGs in flight
                v1[m] = s[1];
            }
            #pragma unroll
            for (int m = 0; m < 8; m++) {
                float2 v = make_float2(v0[m], v1[m]);
                uint32_t hp = cvt_hi(v);
                uint32_t lp = cvt_lo(v, hp);
                uint32_t o = (uint32_t)(lv[m] * RSTRIDE + kv[m]) * 2;
                *reinterpret_cast<uint32_t*>(smem + OFF_WHI + o) = hp;
                *reinterpret_cast<uint32_t*>(smem + OFF_WLO + o) = lp;
            }
        }
        bias_s[t] = pg[t * PROW_SRC + IN_F];
    }

    // ---- x A-fragments straight from gmem into registers (no smem) ----
    const int wid = t >> 5, lane = t & 31;
    const int j0 = (wid >> 1) * 16;
    const int l0 = (wid & 1) * 64;
    const int g = lane >> 2, tg = lane & 3;

    uint32_t ahi[32], alo[32];            // [row01][m]: m = k-octet (2tg + 8m)
    {
        const float* xg = x_in + (size_t)i * (J_DIM * IN_F);
        const float* r0p = xg + (j0 + g) * IN_F + 2 * tg;
        const float* r1p = xg + (j0 + 8 + g) * IN_F + 2 * tg;
        #pragma unroll
        for (int m = 0; m < 16; m++) {
            float2 u0 = *reinterpret_cast<const float2*>(r0p + 8 * m);
            float2 u1 = *reinterpret_cast<const float2*>(r1p + 8 * m);
            ahi[m]      = cvt_hi(u0);  alo[m]      = cvt_lo(u0, ahi[m]);
            ahi[16 + m] = cvt_hi(u1);  alo[16 + m] = cvt_lo(u1, ahi[16 + m]);
        }
    }

    __syncthreads();                       // W planes ready

    // ---- compute: warp -> j-rows [j0,j0+16) x l-cols [l0,l0+64) ----
    float c[8][4];
    #pragma unroll
    for (int nt = 0; nt < 8; nt++)
        #pragma unroll
        for (int q = 0; q < 4; q++) c[nt][q] = 0.0f;

    // ldmatrix B lane->row map (tiles: (n0-7,k0)(n0-7,k8)(n8-15,k0)(n8-15,k8))
    const int brow  = l0 + (lane & 7) + (lane >> 4) * 8;
    const int bkoff = ((lane >> 3) & 1) * 8;
    uint32_t b_hi = sb + OFF_WHI + (uint32_t)(brow * RSTRIDE + bkoff) * 2;
    uint32_t b_lo = sb + OFF_WLO + (uint32_t)(brow * RSTRIDE + bkoff) * 2;
    const uint32_t PSTEP = 16 * RSTRIDE * 2;

    #pragma unroll
    for (int ks = 0; ks < 8; ks++) {
        const uint32_t ko = (uint32_t)ks * 32;
        // A fragment regs for this kstep (order: (g,klo),(g+8,klo),(g,khi),(g+8,khi))
        const uint32_t ah0 = ahi[2 * ks],     ah1 = ahi[16 + 2 * ks];
        const uint32_t ah2 = ahi[2 * ks + 1], ah3 = ahi[16 + 2 * ks + 1];
        const uint32_t al0 = alo[2 * ks],     al1 = alo[16 + 2 * ks];
        const uint32_t al2 = alo[2 * ks + 1], al3 = alo[16 + 2 * ks + 1];

        uint32_t bh[4][4], bl[4][4];
        #pragma unroll
        for (int p = 0; p < 4; p++) {
            ldmx4(bh[p], b_hi + p * PSTEP + ko);
            ldmx4(bl[p], b_lo + p * PSTEP + ko);
        }

        #pragma unroll
        for (int nt = 0; nt < 8; nt++) {
            const int p = nt >> 1;
            const int q = (nt & 1) * 2;
            mma_bf16(c[nt], ah0, ah1, ah2, ah3, bh[p][q], bh[p][q + 1]);   // hi*hi
            mma_bf16(c[nt], ah0, ah1, ah2, ah3, bl[p][q], bl[p][q + 1]);   // hi*lo
            mma_bf16(c[nt], al0, al1, al2, al3, bh[p][q], bh[p][q + 1]);   // lo*hi
        }
    }

    // ---- epilogue (verified in R12): c0,c1 -> row j0+g; c2,c3 -> row j0+g+8 ----
    float* og = out + (size_t)i * (J_DIM * OUT_F);
    #pragma unroll
    for (int nt = 0; nt < 8; nt++) {
        const int l = l0 + nt * 8 + 2 * tg;
        const float2 b2 = *reinterpret_cast<const float2*>(bias_s + l);
        float2 r0; r0.x = c[nt][0] + b2.x; r0.y = c[nt][1] + b2.y;
        float2 r1; r1.x = c[nt][2] + b2.x; r1.y = c[nt][3] + b2.y;
        *reinterpret_cast<float2*>(og + (j0 + g)     * OUT_F + l) = r0;
        *reinterpret_cast<float2*>(og + (j0 + g + 8) * OUT_F + l) = r1;
    }
}

extern "C" void kernel_launch(void* const* d_in, const int* in_sizes, int n_in,
                              void* d_out, int out_size)
{
    const float* x_in   = (const float*)d_in[0];
    const int*   inds   = (const int*)d_in[1];
    const float* params = (const float*)d_in[2];
    float*       out    = (float*)d_out;

    static bool attr_set = false;
    if (!attr_set) {
        cudaFuncSetAttribute(multidense_kernel,
                             cudaFuncAttributeMaxDynamicSharedMemorySize, SMEM_BYTES);
        attr_set = true;
    }

    multidense_kernel<<<I_DIM, 128, SMEM_BYTES>>>(x_in, inds, params, out);
}